// round 5
// baseline (speedup 1.0000x reference)
#include <cuda_runtime.h>
#include <math.h>

#define B_SZ    2
#define S_LEN   2048
#define D_MODEL 1024
#define NHEAD   16
#define HDIM    64
#define M_ROWS  (B_SZ * S_LEN)   // 4096

// ---------------- scratch (device-side only; never passed from host) -------
__device__ float g_q[M_ROWS * D_MODEL];
__device__ float g_k[M_ROWS * D_MODEL];
__device__ float g_v[M_ROWS * D_MODEL];
__device__ float g_attn[M_ROWS * D_MODEL];
__device__ float2 g_rope[S_LEN * 32];     // (cos, sin) per (s, d)

// ========== tiled GEMM core: C[m][n] = sum_k A[m][k] * W[n][k] ==========
// Block: 256 threads (16x16). Tile: M16 x N64, K-tile 16. 4 outputs/thread.
__device__ __forceinline__ void gemm_mt(const float* __restrict__ A,
                                        const float* __restrict__ W,
                                        float* __restrict__ C) {
    __shared__ float As[16][17];
    __shared__ float Ws[64][17];

    const int tx = threadIdx.x & 15;
    const int ty = threadIdx.x >> 4;
    const int m0 = blockIdx.y * 16;
    const int n0 = blockIdx.x * 64;

    float acc0 = 0.f, acc1 = 0.f, acc2 = 0.f, acc3 = 0.f;

    for (int k0 = 0; k0 < D_MODEL; k0 += 16) {
        As[ty][tx] = A[(size_t)(m0 + ty) * D_MODEL + k0 + tx];
#pragma unroll
        for (int rep = 0; rep < 4; rep++) {
            int r = ty + rep * 16;
            Ws[r][tx] = W[(size_t)(n0 + r) * D_MODEL + k0 + tx];
        }
        __syncthreads();

#pragma unroll
        for (int k = 0; k < 16; k++) {
            float a = As[ty][k];
            acc0 = fmaf(a, Ws[tx +  0][k], acc0);
            acc1 = fmaf(a, Ws[tx + 16][k], acc1);
            acc2 = fmaf(a, Ws[tx + 32][k], acc2);
            acc3 = fmaf(a, Ws[tx + 48][k], acc3);
        }
        __syncthreads();
    }

    float* crow = C + (size_t)(m0 + ty) * D_MODEL + n0;
    crow[tx +  0] = acc0;
    crow[tx + 16] = acc1;
    crow[tx + 32] = acc2;
    crow[tx + 48] = acc3;
}

__global__ __launch_bounds__(256) void gemm_qkv_kernel(const float* __restrict__ A,
                                                       const float* __restrict__ Wq,
                                                       const float* __restrict__ Wk,
                                                       const float* __restrict__ Wv) {
    const float* W = (blockIdx.z == 0) ? Wq : (blockIdx.z == 1) ? Wk : Wv;
    float* C       = (blockIdx.z == 0) ? g_q : (blockIdx.z == 1) ? g_k : g_v;
    gemm_mt(A, W, C);
}

__global__ __launch_bounds__(256) void gemm_o_kernel(const float* __restrict__ Wo,
                                                     float* __restrict__ C) {
    gemm_mt(g_attn, Wo, C);
}

// ========== RoPE table: ACCURATE trig (double path; immune to fast-math) ====
// Matches reference fp32 rounding: inv_freq rounded to fp32, angle = fp32
// product, then accurate sincos of that fp32 angle.
__global__ __launch_bounds__(256) void rope_table_kernel() {
    int idx = blockIdx.x * 256 + threadIdx.x;      // 0 .. S_LEN*32-1
    if (idx >= S_LEN * 32) return;
    int d = idx & 31;
    int s = idx >> 5;

    double f64   = pow(10000.0, -(double)d / 32.0);
    float  inv32 = (float)f64;                     // fp32 inv_freq (as jnp)
    float  ang32 = (float)s * inv32;               // fp32 product  (as jnp)
    double c, sn;
    sincos((double)ang32, &sn, &c);                // accurate trig of fp32 angle
    g_rope[idx] = make_float2((float)c, (float)sn);
}

// ================= RoPE apply (in-place on g_q, g_k) =================
// One thread per (row, head, d<32) pair.
__global__ __launch_bounds__(256) void rope_kernel() {
    int idx = blockIdx.x * 256 + threadIdx.x;   // total = M_ROWS*16*32
    int d    = idx & 31;
    int rest = idx >> 5;
    int h    = rest & 15;
    int row  = rest >> 4;          // b*S + s
    int s    = row & (S_LEN - 1);

    float2 cs = g_rope[s * 32 + d];
    float c = cs.x, sn = cs.y;

    size_t i1 = (size_t)row * D_MODEL + h * HDIM + d;
    size_t i2 = i1 + 32;

    float q1 = g_q[i1], q2 = g_q[i2];
    g_q[i1] = q1 * c - q2 * sn;
    g_q[i2] = q2 * c + q1 * sn;

    float k1 = g_k[i1], k2 = g_k[i2];
    g_k[i1] = k1 * c - k2 * sn;
    g_k[i2] = k2 * c + k1 * sn;
}

// ================= Flash attention (1 thread = 1 query row) ======
__global__ __launch_bounds__(128) void attn_kernel() {
    __shared__ float Ks[32][64];
    __shared__ float Vs[32][64];

    const int tid = threadIdx.x;
    const int b = blockIdx.z, h = blockIdx.y;
    const int r = blockIdx.x * 128 + tid;
    const size_t hoff = (size_t)h * HDIM;

    const float* Qrow = g_q + ((size_t)(b * S_LEN + r)) * D_MODEL + hoff;
    float q[64];
#pragma unroll
    for (int d4 = 0; d4 < 16; d4++) {
        float4 v = *(const float4*)(Qrow + d4 * 4);
        q[d4 * 4 + 0] = v.x; q[d4 * 4 + 1] = v.y;
        q[d4 * 4 + 2] = v.z; q[d4 * 4 + 3] = v.w;
    }

    float acc[64];
#pragma unroll
    for (int d = 0; d < 64; d++) acc[d] = 0.f;
    float m = -INFINITY, l = 0.f;

    for (int kt = 0; kt < S_LEN; kt += 32) {
        const float* Kb = g_k + ((size_t)(b * S_LEN + kt)) * D_MODEL + hoff;
        const float* Vb = g_v + ((size_t)(b * S_LEN + kt)) * D_MODEL + hoff;

        __syncthreads();
#pragma unroll
        for (int i = 0; i < 4; i++) {
            int li  = tid + i * 128;
            int row = li >> 4;
            int ds  = (li & 15) * 4;
            *(float4*)&Ks[row][ds] = *(const float4*)(Kb + (size_t)row * D_MODEL + ds);
            *(float4*)&Vs[row][ds] = *(const float4*)(Vb + (size_t)row * D_MODEL + ds);
        }
        __syncthreads();

        float s[32];
#pragma unroll
        for (int kk = 0; kk < 32; kk++) {
            float a0 = 0.f;
#pragma unroll
            for (int d4 = 0; d4 < 16; d4++) {
                float4 kv = *(const float4*)&Ks[kk][d4 * 4];
                a0 = fmaf(q[d4 * 4 + 0], kv.x, a0);
                a0 = fmaf(q[d4 * 4 + 1], kv.y, a0);
                a0 = fmaf(q[d4 * 4 + 2], kv.z, a0);
                a0 = fmaf(q[d4 * 4 + 3], kv.w, a0);
            }
            s[kk] = a0 * 0.125f;
        }

        float mt = s[0];
#pragma unroll
        for (int kk = 1; kk < 32; kk++) mt = fmaxf(mt, s[kk]);
        float mnew = fmaxf(m, mt);
        float al = __expf(m - mnew);
        l *= al;
#pragma unroll
        for (int d = 0; d < 64; d++) acc[d] *= al;

#pragma unroll
        for (int kk = 0; kk < 32; kk++) {
            float p = __expf(s[kk] - mnew);
            l += p;
#pragma unroll
            for (int d4 = 0; d4 < 16; d4++) {
                float4 vv = *(const float4*)&Vs[kk][d4 * 4];
                acc[d4 * 4 + 0] = fmaf(p, vv.x, acc[d4 * 4 + 0]);
                acc[d4 * 4 + 1] = fmaf(p, vv.y, acc[d4 * 4 + 1]);
                acc[d4 * 4 + 2] = fmaf(p, vv.z, acc[d4 * 4 + 2]);
                acc[d4 * 4 + 3] = fmaf(p, vv.w, acc[d4 * 4 + 3]);
            }
        }
        m = mnew;
    }

    float inv = 1.f / l;
    float* Orow = g_attn + ((size_t)(b * S_LEN + r)) * D_MODEL + hoff;
#pragma unroll
    for (int d4 = 0; d4 < 16; d4++) {
        float4 o = make_float4(acc[d4 * 4 + 0] * inv, acc[d4 * 4 + 1] * inv,
                               acc[d4 * 4 + 2] * inv, acc[d4 * 4 + 3] * inv);
        *(float4*)(Orow + d4 * 4) = o;
    }
}

// ================= launch =================
extern "C" void kernel_launch(void* const* d_in, const int* in_sizes, int n_in,
                              void* d_out, int out_size) {
    // hidden_states = unique B*S*D input; weights = D*D inputs in order.
    int xi = -1;
    for (int i = 0; i < n_in; i++)
        if (in_sizes[i] == M_ROWS * D_MODEL) { xi = i; break; }
    if (xi < 0) xi = 0;
    const float* w[4] = {0, 0, 0, 0};
    int wn = 0;
    for (int i = 0; i < n_in && wn < 4; i++)
        if (i != xi && in_sizes[i] == D_MODEL * D_MODEL)
            w[wn++] = (const float*)d_in[i];

    const float* x  = (const float*)d_in[xi];
    const float* Wq = w[0];
    const float* Wk = w[1];
    const float* Wv = w[2];
    const float* Wo = w[3];
    float* out = (float*)d_out;

    dim3 gqkv(D_MODEL / 64, M_ROWS / 16, 3);     // (16, 256, 3)
    gemm_qkv_kernel<<<gqkv, 256>>>(x, Wq, Wk, Wv);

    rope_table_kernel<<<(S_LEN * 32) / 256, 256>>>();        // 256 blocks
    rope_kernel<<<(M_ROWS * NHEAD * 32) / 256, 256>>>();     // 8192 blocks

    dim3 gattn(S_LEN / 128, NHEAD, B_SZ);        // (16, 16, 2)
    attn_kernel<<<gattn, 128>>>();

    dim3 go(D_MODEL / 64, M_ROWS / 16, 1);       // (16, 256)
    gemm_o_kernel<<<go, 256>>>(Wo, out);
}

// round 7
// speedup vs baseline: 2.0053x; 2.0053x over previous
#include <cuda_runtime.h>
#include <math.h>

#define B_SZ    2
#define S_LEN   2048
#define D_MODEL 1024
#define NHEAD   16
#define HDIM    64
#define M_ROWS  (B_SZ * S_LEN)   // 4096

// ---------------- scratch (device-side only; never passed from host) -------
__device__ float g_q[M_ROWS * D_MODEL];
__device__ float g_k[M_ROWS * D_MODEL];
__device__ float g_v[M_ROWS * D_MODEL];
__device__ float g_attn[M_ROWS * D_MODEL];
__device__ float2 g_rope[S_LEN * 32];     // (cos, sin) per (s, d)

// ========== SGEMM: C[M,N] = A[M,K] * W[N,K]^T ==========
// BM=BN=128, BK=16, 256 threads, 8x8 per thread. (Proven correct in R1/R4.)
__device__ __forceinline__ void sgemm_tile(const float* __restrict__ A,
                                           const float* __restrict__ W,
                                           float* __restrict__ C,
                                           float (*As)[132], float (*Bs)[132]) {
    const int K = D_MODEL, N = D_MODEL;
    const int tid = threadIdx.x;
    const int tx = tid & 15;
    const int ty = tid >> 4;
    const int bx = blockIdx.x;
    const int by = blockIdx.y;

    const float* Ablk = A + (size_t)(by * 128) * K;
    const float* Wblk = W + (size_t)(bx * 128) * K;

    const int lrow = tid >> 2;        // 0..63
    const int lk4  = (tid & 3) * 4;   // 0,4,8,12

    float acc[8][8];
#pragma unroll
    for (int i = 0; i < 8; i++)
#pragma unroll
        for (int j = 0; j < 8; j++) acc[i][j] = 0.f;

    for (int k0 = 0; k0 < K; k0 += 16) {
#pragma unroll
        for (int half = 0; half < 2; half++) {
            int row = lrow + half * 64;
            float4 av = *(const float4*)(Ablk + (size_t)row * K + k0 + lk4);
            float4 bv = *(const float4*)(Wblk + (size_t)row * K + k0 + lk4);
            As[lk4 + 0][row] = av.x; As[lk4 + 1][row] = av.y;
            As[lk4 + 2][row] = av.z; As[lk4 + 3][row] = av.w;
            Bs[lk4 + 0][row] = bv.x; Bs[lk4 + 1][row] = bv.y;
            Bs[lk4 + 2][row] = bv.z; Bs[lk4 + 3][row] = bv.w;
        }
        __syncthreads();

#pragma unroll 8
        for (int kk = 0; kk < 16; kk++) {
            float a[8], b[8];
            *(float4*)(a)     = *(const float4*)&As[kk][ty * 8];
            *(float4*)(a + 4) = *(const float4*)&As[kk][ty * 8 + 4];
            *(float4*)(b)     = *(const float4*)&Bs[kk][tx * 8];
            *(float4*)(b + 4) = *(const float4*)&Bs[kk][tx * 8 + 4];
#pragma unroll
            for (int i = 0; i < 8; i++)
#pragma unroll
                for (int j = 0; j < 8; j++)
                    acc[i][j] = fmaf(a[i], b[j], acc[i][j]);
        }
        __syncthreads();
    }

#pragma unroll
    for (int i = 0; i < 8; i++) {
        float* crow = C + (size_t)(by * 128 + ty * 8 + i) * N + bx * 128 + tx * 8;
        *(float4*)(crow)     = make_float4(acc[i][0], acc[i][1], acc[i][2], acc[i][3]);
        *(float4*)(crow + 4) = make_float4(acc[i][4], acc[i][5], acc[i][6], acc[i][7]);
    }
}

__global__ __launch_bounds__(256) void sgemm_qkv_kernel(const float* __restrict__ A,
                                                        const float* __restrict__ Wq,
                                                        const float* __restrict__ Wk,
                                                        const float* __restrict__ Wv) {
    __shared__ float As[16][132];
    __shared__ float Bs[16][132];
    const float* W = (blockIdx.z == 0) ? Wq : (blockIdx.z == 1) ? Wk : Wv;
    float* C       = (blockIdx.z == 0) ? g_q : (blockIdx.z == 1) ? g_k : g_v;
    sgemm_tile(A, W, C, As, Bs);
}

__global__ __launch_bounds__(256) void sgemm_o_kernel(const float* __restrict__ Wo,
                                                      float* __restrict__ C) {
    __shared__ float As[16][132];
    __shared__ float Bs[16][132];
    sgemm_tile(g_attn, Wo, C, As, Bs);
}

// ========== RoPE table: accurate trig (double path; immune to fast-math) ====
__global__ __launch_bounds__(256) void rope_table_kernel() {
    int idx = blockIdx.x * 256 + threadIdx.x;      // 0 .. S_LEN*32-1
    if (idx >= S_LEN * 32) return;
    int d = idx & 31;
    int s = idx >> 5;

    double f64   = pow(10000.0, -(double)d / 32.0);
    float  inv32 = (float)f64;
    float  ang32 = (float)s * inv32;
    double c, sn;
    sincos((double)ang32, &sn, &c);
    g_rope[idx] = make_float2((float)c, (float)sn);
}

// ================= RoPE apply (in-place on g_q, g_k) =================
__global__ __launch_bounds__(256) void rope_kernel() {
    int idx = blockIdx.x * 256 + threadIdx.x;   // total = M_ROWS*16*32
    int d    = idx & 31;
    int rest = idx >> 5;
    int h    = rest & 15;
    int row  = rest >> 4;          // b*S + s
    int s    = row & (S_LEN - 1);

    float2 cs = g_rope[s * 32 + d];
    float c = cs.x, sn = cs.y;

    size_t i1 = (size_t)row * D_MODEL + h * HDIM + d;
    size_t i2 = i1 + 32;

    float q1 = g_q[i1], q2 = g_q[i2];
    g_q[i1] = q1 * c - q2 * sn;
    g_q[i2] = q2 * c + q1 * sn;

    float k1 = g_k[i1], k2 = g_k[i2];
    g_k[i1] = k1 * c - k2 * sn;
    g_k[i2] = k2 * c + k1 * sn;
}

// ================= Flash attention (4x4 fragment, 64-row Q tile) ======
// One CTA per (batch, head, 64-row query tile). 256 threads.
// Smem 48KB: qsT[64][64], ksT[64][64] (reused as P^T), vs[64][64].
__global__ __launch_bounds__(256) void attn_kernel() {
    __shared__ float qsT[64 * 64];   // qsT[d][r]
    __shared__ float ksT[64 * 64];   // ksT[d][c]; later P^T[c][r]
    __shared__ float vs [64 * 64];   // vs[s][d]

    const int tid = threadIdx.x;
    const int b = blockIdx.z, h = blockIdx.y;
    const int q0 = blockIdx.x * 64;
    const size_t hoff = (size_t)h * HDIM;

    const float* Qb = g_q + ((size_t)(b * S_LEN + q0)) * D_MODEL + hoff;

#pragma unroll
    for (int i = 0; i < 4; i++) {
        int li  = tid + i * 256;
        int row = li >> 4;
        int ds  = (li & 15) * 4;
        float4 v = *(const float4*)(Qb + (size_t)row * D_MODEL + ds);
        qsT[(ds + 0) * 64 + row] = v.x;
        qsT[(ds + 1) * 64 + row] = v.y;
        qsT[(ds + 2) * 64 + row] = v.z;
        qsT[(ds + 3) * 64 + row] = v.w;
    }

    const int r0 = (tid >> 4) * 4;
    const int c0 = (tid & 15) * 4;

    float m_run[4], l_run[4], acc[4][4];
#pragma unroll
    for (int i = 0; i < 4; i++) {
        m_run[i] = -INFINITY; l_run[i] = 0.f;
#pragma unroll
        for (int j = 0; j < 4; j++) acc[i][j] = 0.f;
    }
    const float scale = 0.125f;

    for (int t = 0; t < S_LEN / 64; t++) {
        const float* Kb = g_k + ((size_t)(b * S_LEN + t * 64)) * D_MODEL + hoff;
        const float* Vb = g_v + ((size_t)(b * S_LEN + t * 64)) * D_MODEL + hoff;

        __syncthreads();
#pragma unroll
        for (int i = 0; i < 4; i++) {
            int li  = tid + i * 256;
            int row = li >> 4;
            int ds  = (li & 15) * 4;
            float4 kv = *(const float4*)(Kb + (size_t)row * D_MODEL + ds);
            ksT[(ds + 0) * 64 + row] = kv.x;
            ksT[(ds + 1) * 64 + row] = kv.y;
            ksT[(ds + 2) * 64 + row] = kv.z;
            ksT[(ds + 3) * 64 + row] = kv.w;
            float4 vv = *(const float4*)(Vb + (size_t)row * D_MODEL + ds);
            *(float4*)&vs[row * 64 + ds] = vv;
        }
        __syncthreads();

        float sc[4][4];
#pragma unroll
        for (int i = 0; i < 4; i++)
#pragma unroll
            for (int j = 0; j < 4; j++) sc[i][j] = 0.f;

#pragma unroll 8
        for (int d = 0; d < 64; d++) {
            float4 qv = *(const float4*)&qsT[d * 64 + r0];
            float4 kv = *(const float4*)&ksT[d * 64 + c0];
            float qa[4] = {qv.x, qv.y, qv.z, qv.w};
            float kb[4] = {kv.x, kv.y, kv.z, kv.w};
#pragma unroll
            for (int i = 0; i < 4; i++)
#pragma unroll
                for (int j = 0; j < 4; j++)
                    sc[i][j] = fmaf(qa[i], kb[j], sc[i][j]);
        }

#pragma unroll
        for (int i = 0; i < 4; i++) {
#pragma unroll
            for (int j = 0; j < 4; j++) sc[i][j] *= scale;
            float mt = fmaxf(fmaxf(sc[i][0], sc[i][1]), fmaxf(sc[i][2], sc[i][3]));
            mt = fmaxf(mt, __shfl_xor_sync(0xffffffffu, mt, 1));
            mt = fmaxf(mt, __shfl_xor_sync(0xffffffffu, mt, 2));
            mt = fmaxf(mt, __shfl_xor_sync(0xffffffffu, mt, 4));
            mt = fmaxf(mt, __shfl_xor_sync(0xffffffffu, mt, 8));
            float mnew = fmaxf(m_run[i], mt);
            float al   = __expf(m_run[i] - mnew);
            float rs   = 0.f;
#pragma unroll
            for (int j = 0; j < 4; j++) {
                sc[i][j] = __expf(sc[i][j] - mnew);
                rs += sc[i][j];
            }
            rs += __shfl_xor_sync(0xffffffffu, rs, 1);
            rs += __shfl_xor_sync(0xffffffffu, rs, 2);
            rs += __shfl_xor_sync(0xffffffffu, rs, 4);
            rs += __shfl_xor_sync(0xffffffffu, rs, 8);
            l_run[i] = l_run[i] * al + rs;
            m_run[i] = mnew;
#pragma unroll
            for (int j = 0; j < 4; j++) acc[i][j] *= al;
        }

        __syncthreads();
#pragma unroll
        for (int j = 0; j < 4; j++) {
            float4 pv = make_float4(sc[0][j], sc[1][j], sc[2][j], sc[3][j]);
            *(float4*)&ksT[(c0 + j) * 64 + r0] = pv;
        }
        __syncthreads();

#pragma unroll 8
        for (int kk = 0; kk < 64; kk++) {
            float4 pv = *(const float4*)&ksT[kk * 64 + r0];
            float4 vv = *(const float4*)&vs[kk * 64 + c0];
            float pa[4] = {pv.x, pv.y, pv.z, pv.w};
            float vb[4] = {vv.x, vv.y, vv.z, vv.w};
#pragma unroll
            for (int i = 0; i < 4; i++)
#pragma unroll
                for (int j = 0; j < 4; j++)
                    acc[i][j] = fmaf(pa[i], vb[j], acc[i][j]);
        }
    }

    float* Ob = g_attn + ((size_t)(b * S_LEN + q0)) * D_MODEL + hoff;
#pragma unroll
    for (int i = 0; i < 4; i++) {
        float inv = 1.f / l_run[i];
        float4 o = make_float4(acc[i][0] * inv, acc[i][1] * inv,
                               acc[i][2] * inv, acc[i][3] * inv);
        *(float4*)(Ob + (size_t)(r0 + i) * D_MODEL + c0) = o;
    }
}

// ================= launch =================
extern "C" void kernel_launch(void* const* d_in, const int* in_sizes, int n_in,
                              void* d_out, int out_size) {
    int xi = -1;
    for (int i = 0; i < n_in; i++)
        if (in_sizes[i] == M_ROWS * D_MODEL) { xi = i; break; }
    if (xi < 0) xi = 0;
    const float* w[4] = {0, 0, 0, 0};
    int wn = 0;
    for (int i = 0; i < n_in && wn < 4; i++)
        if (i != xi && in_sizes[i] == D_MODEL * D_MODEL)
            w[wn++] = (const float*)d_in[i];

    const float* x  = (const float*)d_in[xi];
    const float* Wq = w[0];
    const float* Wk = w[1];
    const float* Wv = w[2];
    const float* Wo = w[3];
    float* out = (float*)d_out;

    dim3 gqkv(D_MODEL / 128, M_ROWS / 128, 3);          // (8, 32, 3)
    sgemm_qkv_kernel<<<gqkv, 256>>>(x, Wq, Wk, Wv);

    rope_table_kernel<<<(S_LEN * 32) / 256, 256>>>();
    rope_kernel<<<(M_ROWS * NHEAD * 32) / 256, 256>>>();

    dim3 gattn(S_LEN / 64, NHEAD, B_SZ);                // (32, 16, 2)
    attn_kernel<<<gattn, 256>>>();

    dim3 go(D_MODEL / 128, M_ROWS / 128, 1);            // (8, 32)
    sgemm_o_kernel<<<go, 256>>>(Wo, out);
}

// round 10
// speedup vs baseline: 2.5282x; 1.2607x over previous
#include <cuda_runtime.h>
#include <cuda_bf16.h>
#include <math.h>
#include <stdint.h>

#define B_SZ    2
#define S_LEN   2048
#define D_MODEL 1024
#define NHEAD   16
#define HDIM    64
#define M_ROWS  (B_SZ * S_LEN)   // 4096
#define WSZ     (D_MODEL * D_MODEL)   // 1M

// ---------------- scratch (device-side only) ----------------
__device__ float  g_q[M_ROWS * D_MODEL];
__device__ float  g_k[M_ROWS * D_MODEL];
__device__ float  g_v[M_ROWS * D_MODEL];
__device__ float  g_attn[M_ROWS * D_MODEL];
__device__ float2 g_rope[S_LEN * 32];
__device__ __nv_bfloat16 g_xhi[M_ROWS * D_MODEL];
__device__ __nv_bfloat16 g_xlo[M_ROWS * D_MODEL];
__device__ __nv_bfloat16 g_whi[4 * WSZ];
__device__ __nv_bfloat16 g_wlo[4 * WSZ];
__device__ __nv_bfloat16 g_ahi[M_ROWS * D_MODEL];
__device__ __nv_bfloat16 g_alo[M_ROWS * D_MODEL];

// ================= warp-MMA helpers (sm_80+ base-target legal) =============
__device__ __forceinline__ uint32_t smem_u32(const void* p) {
    uint32_t a;
    asm("{ .reg .u64 t; cvta.to.shared.u64 t, %1; cvt.u32.u64 %0, t; }" : "=r"(a) : "l"(p));
    return a;
}
__device__ __forceinline__ void ldsm_x4(uint32_t& r0, uint32_t& r1, uint32_t& r2, uint32_t& r3,
                                        uint32_t addr) {
    asm volatile("ldmatrix.sync.aligned.m8n8.x4.shared.b16 {%0,%1,%2,%3}, [%4];"
                 : "=r"(r0), "=r"(r1), "=r"(r2), "=r"(r3) : "r"(addr));
}
__device__ __forceinline__ void mma16816(float* c, const uint32_t* a, const uint32_t* b) {
    asm volatile(
        "mma.sync.aligned.m16n8k16.row.col.f32.bf16.bf16.f32 "
        "{%0,%1,%2,%3}, {%4,%5,%6,%7}, {%8,%9}, {%0,%1,%2,%3};"
        : "+f"(c[0]), "+f"(c[1]), "+f"(c[2]), "+f"(c[3])
        : "r"(a[0]), "r"(a[1]), "r"(a[2]), "r"(a[3]), "r"(b[0]), "r"(b[1]));
}

// smem tile stride: 40 bf16 (80B) -> ldmatrix row addresses conflict-free
#define TSTR 40

// lane address for ldmatrix.x4 covering a 16x16 bf16 block at (row0, col0)
__device__ __forceinline__ uint32_t ldsm_addr(uint32_t base, int row0, int col0, int lane) {
    int sub = lane >> 3, r8 = lane & 7;
    int row = row0 + r8 + (sub & 1) * 8;
    int col = col0 + (sub >> 1) * 8;
    return base + (uint32_t)(row * TSTR + col) * 2;
}

// ============== tensor GEMM: C[M,N] = A[M,K] * W[N,K]^T (bf16 3-term split) =
// CTA tile 128x128, 8 warps, warp tile 64x32 (4x4 m16n8 atoms), K-chunk 32.
__device__ __forceinline__ void tgemm_tile(const __nv_bfloat16* __restrict__ Ahi,
                                           const __nv_bfloat16* __restrict__ Alo,
                                           const __nv_bfloat16* __restrict__ Bhi,
                                           const __nv_bfloat16* __restrict__ Blo,
                                           float* __restrict__ C, int m0, int n0) {
    __shared__ __nv_bfloat16 sAh[128 * TSTR];
    __shared__ __nv_bfloat16 sAl[128 * TSTR];
    __shared__ __nv_bfloat16 sBh[128 * TSTR];
    __shared__ __nv_bfloat16 sBl[128 * TSTR];

    const int tid  = threadIdx.x;
    const int lane = tid & 31;
    const int wid  = tid >> 5;
    const int wm   = (wid & 1) * 64;     // warp M offset in CTA tile
    const int wn   = (wid >> 1) * 32;    // warp N offset

    const uint32_t bAh = smem_u32(sAh), bAl = smem_u32(sAl);
    const uint32_t bBh = smem_u32(sBh), bBl = smem_u32(sBl);

    float acc[4][4][4];
#pragma unroll
    for (int i = 0; i < 4; i++)
#pragma unroll
        for (int j = 0; j < 4; j++)
#pragma unroll
            for (int r = 0; r < 4; r++) acc[i][j][r] = 0.f;

    for (int kb = 0; kb < D_MODEL; kb += 32) {
        __syncthreads();
        // load A/B tiles: 128 rows x 32 bf16, 2 x uint4 per thread per buffer
#pragma unroll
        for (int i = 0; i < 2; i++) {
            int li  = tid + i * 256;          // 0..511
            int row = li >> 2;                // 0..127
            int c8  = (li & 3) * 8;           // 0,8,16,24
            size_t ga = (size_t)(m0 + row) * D_MODEL + kb + c8;
            size_t gb = (size_t)(n0 + row) * D_MODEL + kb + c8;
            *(uint4*)&sAh[row * TSTR + c8] = *(const uint4*)(Ahi + ga);
            *(uint4*)&sAl[row * TSTR + c8] = *(const uint4*)(Alo + ga);
            *(uint4*)&sBh[row * TSTR + c8] = *(const uint4*)(Bhi + gb);
            *(uint4*)&sBl[row * TSTR + c8] = *(const uint4*)(Blo + gb);
        }
        __syncthreads();

#pragma unroll
        for (int ks = 0; ks < 2; ks++) {
            const int kk = ks * 16;
            uint32_t afh[4][4], afl[4][4];
#pragma unroll
            for (int ma = 0; ma < 4; ma++) {
                uint32_t ah = ldsm_addr(bAh, wm + ma * 16, kk, lane);
                uint32_t al = ldsm_addr(bAl, wm + ma * 16, kk, lane);
                ldsm_x4(afh[ma][0], afh[ma][1], afh[ma][2], afh[ma][3], ah);
                ldsm_x4(afl[ma][0], afl[ma][1], afl[ma][2], afl[ma][3], al);
            }
            uint32_t bfh[4][2], bfl[4][2];
#pragma unroll
            for (int p = 0; p < 2; p++) {     // each x4 covers two n-atoms
                uint32_t r0, r1, r2, r3;
                ldsm_x4(r0, r1, r2, r3, ldsm_addr(bBh, wn + p * 16, kk, lane));
                bfh[p * 2 + 0][0] = r0; bfh[p * 2 + 0][1] = r2;
                bfh[p * 2 + 1][0] = r1; bfh[p * 2 + 1][1] = r3;
                ldsm_x4(r0, r1, r2, r3, ldsm_addr(bBl, wn + p * 16, kk, lane));
                bfl[p * 2 + 0][0] = r0; bfl[p * 2 + 0][1] = r2;
                bfl[p * 2 + 1][0] = r1; bfl[p * 2 + 1][1] = r3;
            }
#pragma unroll
            for (int ma = 0; ma < 4; ma++)
#pragma unroll
                for (int na = 0; na < 4; na++) {
                    mma16816(acc[ma][na], afh[ma], bfh[na]);   // hi*hi
                    mma16816(acc[ma][na], afh[ma], bfl[na]);   // hi*lo
                    mma16816(acc[ma][na], afl[ma], bfh[na]);   // lo*hi
                }
        }
    }

    // epilogue: c0 (r, c), c1 (r, c+1), c2 (r+8, c), c3 (r+8, c+1)
#pragma unroll
    for (int ma = 0; ma < 4; ma++)
#pragma unroll
        for (int na = 0; na < 4; na++) {
            int r = m0 + wm + ma * 16 + (lane >> 2);
            int c = n0 + wn + na * 8 + (lane & 3) * 2;
            float* p0 = C + (size_t)r * D_MODEL + c;
            float* p1 = C + (size_t)(r + 8) * D_MODEL + c;
            *(float2*)p0 = make_float2(acc[ma][na][0], acc[ma][na][1]);
            *(float2*)p1 = make_float2(acc[ma][na][2], acc[ma][na][3]);
        }
}

__global__ __launch_bounds__(256) void tgemm_qkv_kernel() {
    int z = blockIdx.z;
    float* C = (z == 0) ? g_q : (z == 1) ? g_k : g_v;
    tgemm_tile(g_xhi, g_xlo, g_whi + (size_t)z * WSZ, g_wlo + (size_t)z * WSZ,
               C, blockIdx.y * 128, blockIdx.x * 128);
}

__global__ __launch_bounds__(256) void tgemm_o_kernel(float* __restrict__ C) {
    tgemm_tile(g_ahi, g_alo, g_whi + (size_t)3 * WSZ, g_wlo + (size_t)3 * WSZ,
               C, blockIdx.y * 128, blockIdx.x * 128);
}

// ================= bf16-split conversions =================
__global__ __launch_bounds__(256) void convert_x_kernel(const float* __restrict__ x) {
    int i = blockIdx.x * 256 + threadIdx.x;
    float v = x[i];
    __nv_bfloat16 hi = __float2bfloat16(v);
    g_xhi[i] = hi;
    g_xlo[i] = __float2bfloat16(v - __bfloat162float(hi));
}
__global__ __launch_bounds__(256) void convert_w_kernel(const float* __restrict__ Wq,
                                                        const float* __restrict__ Wk,
                                                        const float* __restrict__ Wv,
                                                        const float* __restrict__ Wo) {
    int i = blockIdx.x * 256 + threadIdx.x;
    int w = i >> 20;
    int e = i & (WSZ - 1);
    const float* W = (w == 0) ? Wq : (w == 1) ? Wk : (w == 2) ? Wv : Wo;
    float v = W[e];
    __nv_bfloat16 hi = __float2bfloat16(v);
    g_whi[i] = hi;
    g_wlo[i] = __float2bfloat16(v - __bfloat162float(hi));
}
__global__ __launch_bounds__(256) void convert_attn_kernel() {
    int i = blockIdx.x * 256 + threadIdx.x;
    float v = g_attn[i];
    __nv_bfloat16 hi = __float2bfloat16(v);
    g_ahi[i] = hi;
    g_alo[i] = __float2bfloat16(v - __bfloat162float(hi));
}

// ========== RoPE table: accurate trig (double path; immune to fast-math) ====
__global__ __launch_bounds__(256) void rope_table_kernel() {
    int idx = blockIdx.x * 256 + threadIdx.x;
    if (idx >= S_LEN * 32) return;
    int d = idx & 31;
    int s = idx >> 5;
    double f64   = pow(10000.0, -(double)d / 32.0);
    float  inv32 = (float)f64;
    float  ang32 = (float)s * inv32;
    double c, sn;
    sincos((double)ang32, &sn, &c);
    g_rope[idx] = make_float2((float)c, (float)sn);
}

__global__ __launch_bounds__(256) void rope_kernel() {
    int idx = blockIdx.x * 256 + threadIdx.x;
    int d    = idx & 31;
    int rest = idx >> 5;
    int h    = rest & 15;
    int row  = rest >> 4;
    int s    = row & (S_LEN - 1);

    float2 cs = g_rope[s * 32 + d];
    float c = cs.x, sn = cs.y;

    size_t i1 = (size_t)row * D_MODEL + h * HDIM + d;
    size_t i2 = i1 + 32;

    float q1 = g_q[i1], q2 = g_q[i2];
    g_q[i1] = q1 * c - q2 * sn;
    g_q[i2] = q2 * c + q1 * sn;

    float k1 = g_k[i1], k2 = g_k[i2];
    g_k[i1] = k1 * c - k2 * sn;
    g_k[i2] = k2 * c + k1 * sn;
}

// ================= Flash attention (4x4 fragment, 64-row Q tile) ======
__global__ __launch_bounds__(256) void attn_kernel() {
    __shared__ float qsT[64 * 64];
    __shared__ float ksT[64 * 64];
    __shared__ float vs [64 * 64];

    const int tid = threadIdx.x;
    const int b = blockIdx.z, h = blockIdx.y;
    const int q0 = blockIdx.x * 64;
    const size_t hoff = (size_t)h * HDIM;

    const float* Qb = g_q + ((size_t)(b * S_LEN + q0)) * D_MODEL + hoff;

#pragma unroll
    for (int i = 0; i < 4; i++) {
        int li  = tid + i * 256;
        int row = li >> 4;
        int ds  = (li & 15) * 4;
        float4 v = *(const float4*)(Qb + (size_t)row * D_MODEL + ds);
        qsT[(ds + 0) * 64 + row] = v.x;
        qsT[(ds + 1) * 64 + row] = v.y;
        qsT[(ds + 2) * 64 + row] = v.z;
        qsT[(ds + 3) * 64 + row] = v.w;
    }

    const int r0 = (tid >> 4) * 4;
    const int c0 = (tid & 15) * 4;

    float m_run[4], l_run[4], acc[4][4];
#pragma unroll
    for (int i = 0; i < 4; i++) {
        m_run[i] = -INFINITY; l_run[i] = 0.f;
#pragma unroll
        for (int j = 0; j < 4; j++) acc[i][j] = 0.f;
    }
    const float scale = 0.125f;

    for (int t = 0; t < S_LEN / 64; t++) {
        const float* Kb = g_k + ((size_t)(b * S_LEN + t * 64)) * D_MODEL + hoff;
        const float* Vb = g_v + ((size_t)(b * S_LEN + t * 64)) * D_MODEL + hoff;

        __syncthreads();
#pragma unroll
        for (int i = 0; i < 4; i++) {
            int li  = tid + i * 256;
            int row = li >> 4;
            int ds  = (li & 15) * 4;
            float4 kv = *(const float4*)(Kb + (size_t)row * D_MODEL + ds);
            ksT[(ds + 0) * 64 + row] = kv.x;
            ksT[(ds + 1) * 64 + row] = kv.y;
            ksT[(ds + 2) * 64 + row] = kv.z;
            ksT[(ds + 3) * 64 + row] = kv.w;
            float4 vv = *(const float4*)(Vb + (size_t)row * D_MODEL + ds);
            *(float4*)&vs[row * 64 + ds] = vv;
        }
        __syncthreads();

        float sc[4][4];
#pragma unroll
        for (int i = 0; i < 4; i++)
#pragma unroll
            for (int j = 0; j < 4; j++) sc[i][j] = 0.f;

#pragma unroll 8
        for (int d = 0; d < 64; d++) {
            float4 qv = *(const float4*)&qsT[d * 64 + r0];
            float4 kv = *(const float4*)&ksT[d * 64 + c0];
            float qa[4] = {qv.x, qv.y, qv.z, qv.w};
            float kb[4] = {kv.x, kv.y, kv.z, kv.w};
#pragma unroll
            for (int i = 0; i < 4; i++)
#pragma unroll
                for (int j = 0; j < 4; j++)
                    sc[i][j] = fmaf(qa[i], kb[j], sc[i][j]);
        }

#pragma unroll
        for (int i = 0; i < 4; i++) {
#pragma unroll
            for (int j = 0; j < 4; j++) sc[i][j] *= scale;
            float mt = fmaxf(fmaxf(sc[i][0], sc[i][1]), fmaxf(sc[i][2], sc[i][3]));
            mt = fmaxf(mt, __shfl_xor_sync(0xffffffffu, mt, 1));
            mt = fmaxf(mt, __shfl_xor_sync(0xffffffffu, mt, 2));
            mt = fmaxf(mt, __shfl_xor_sync(0xffffffffu, mt, 4));
            mt = fmaxf(mt, __shfl_xor_sync(0xffffffffu, mt, 8));
            float mnew = fmaxf(m_run[i], mt);
            float al   = __expf(m_run[i] - mnew);
            float rs   = 0.f;
#pragma unroll
            for (int j = 0; j < 4; j++) {
                sc[i][j] = __expf(sc[i][j] - mnew);
                rs += sc[i][j];
            }
            rs += __shfl_xor_sync(0xffffffffu, rs, 1);
            rs += __shfl_xor_sync(0xffffffffu, rs, 2);
            rs += __shfl_xor_sync(0xffffffffu, rs, 4);
            rs += __shfl_xor_sync(0xffffffffu, rs, 8);
            l_run[i] = l_run[i] * al + rs;
            m_run[i] = mnew;
#pragma unroll
            for (int j = 0; j < 4; j++) acc[i][j] *= al;
        }

        __syncthreads();
#pragma unroll
        for (int j = 0; j < 4; j++) {
            float4 pv = make_float4(sc[0][j], sc[1][j], sc[2][j], sc[3][j]);
            *(float4*)&ksT[(c0 + j) * 64 + r0] = pv;
        }
        __syncthreads();

#pragma unroll 8
        for (int kk = 0; kk < 64; kk++) {
            float4 pv = *(const float4*)&ksT[kk * 64 + r0];
            float4 vv = *(const float4*)&vs[kk * 64 + c0];
            float pa[4] = {pv.x, pv.y, pv.z, pv.w};
            float vb[4] = {vv.x, vv.y, vv.z, vv.w};
#pragma unroll
            for (int i = 0; i < 4; i++)
#pragma unroll
                for (int j = 0; j < 4; j++)
                    acc[i][j] = fmaf(pa[i], vb[j], acc[i][j]);
        }
    }

    float* Ob = g_attn + ((size_t)(b * S_LEN + q0)) * D_MODEL + hoff;
#pragma unroll
    for (int i = 0; i < 4; i++) {
        float inv = 1.f / l_run[i];
        float4 o = make_float4(acc[i][0] * inv, acc[i][1] * inv,
                               acc[i][2] * inv, acc[i][3] * inv);
        *(float4*)(Ob + (size_t)(r0 + i) * D_MODEL + c0) = o;
    }
}

// ================= launch =================
extern "C" void kernel_launch(void* const* d_in, const int* in_sizes, int n_in,
                              void* d_out, int out_size) {
    int xi = -1;
    for (int i = 0; i < n_in; i++)
        if (in_sizes[i] == M_ROWS * D_MODEL) { xi = i; break; }
    if (xi < 0) xi = 0;
    const float* w[4] = {0, 0, 0, 0};
    int wn = 0;
    for (int i = 0; i < n_in && wn < 4; i++)
        if (i != xi && in_sizes[i] == WSZ)
            w[wn++] = (const float*)d_in[i];

    const float* x  = (const float*)d_in[xi];
    float* out = (float*)d_out;

    convert_x_kernel<<<(M_ROWS * D_MODEL) / 256, 256>>>(x);
    convert_w_kernel<<<(4 * WSZ) / 256, 256>>>(w[0], w[1], w[2], w[3]);

    dim3 gqkv(D_MODEL / 128, M_ROWS / 128, 3);      // (8, 32, 3)
    tgemm_qkv_kernel<<<gqkv, 256>>>();

    rope_table_kernel<<<(S_LEN * 32) / 256, 256>>>();
    rope_kernel<<<(M_ROWS * NHEAD * 32) / 256, 256>>>();

    dim3 gattn(S_LEN / 64, NHEAD, B_SZ);            // (32, 16, 2)
    attn_kernel<<<gattn, 256>>>();

    convert_attn_kernel<<<(M_ROWS * D_MODEL) / 256, 256>>>();

    dim3 go(D_MODEL / 128, M_ROWS / 128, 1);        // (8, 32)
    tgemm_o_kernel<<<go, 256>>>(out);
}

// round 11
// speedup vs baseline: 4.3961x; 1.7389x over previous
#include <cuda_runtime.h>
#include <cuda_bf16.h>
#include <math.h>
#include <stdint.h>

#define B_SZ    2
#define S_LEN   2048
#define D_MODEL 1024
#define NHEAD   16
#define HDIM    64
#define M_ROWS  (B_SZ * S_LEN)   // 4096
#define WSZ     (D_MODEL * D_MODEL)   // 1M
#define HS      (B_SZ * NHEAD)   // 32 heads total

// ---------------- scratch (device-side only) ----------------
__device__ float  g_q[M_ROWS * D_MODEL];
__device__ float  g_k[M_ROWS * D_MODEL];
__device__ float  g_v[M_ROWS * D_MODEL];
__device__ float2 g_rope[S_LEN * 32];
__device__ __nv_bfloat16 g_xhi[M_ROWS * D_MODEL];
__device__ __nv_bfloat16 g_xlo[M_ROWS * D_MODEL];
__device__ __nv_bfloat16 g_whi[4 * WSZ];
__device__ __nv_bfloat16 g_wlo[4 * WSZ];
__device__ __nv_bfloat16 g_ahi[M_ROWS * D_MODEL];
__device__ __nv_bfloat16 g_alo[M_ROWS * D_MODEL];
// head-major roped q/k: [bh][s][d]
__device__ __nv_bfloat16 g_qhi[HS * S_LEN * HDIM];
__device__ __nv_bfloat16 g_qlo[HS * S_LEN * HDIM];
__device__ __nv_bfloat16 g_khi[HS * S_LEN * HDIM];
__device__ __nv_bfloat16 g_klo[HS * S_LEN * HDIM];
// transposed v: [bh][d][s]
__device__ __nv_bfloat16 g_vthi[HS * HDIM * S_LEN];
__device__ __nv_bfloat16 g_vtlo[HS * HDIM * S_LEN];

// ================= warp-MMA helpers (sm_80+ base-target legal) =============
__device__ __forceinline__ uint32_t smem_u32(const void* p) {
    uint32_t a;
    asm("{ .reg .u64 t; cvta.to.shared.u64 t, %1; cvt.u32.u64 %0, t; }" : "=r"(a) : "l"(p));
    return a;
}
__device__ __forceinline__ void ldsm_x4(uint32_t& r0, uint32_t& r1, uint32_t& r2, uint32_t& r3,
                                        uint32_t addr) {
    asm volatile("ldmatrix.sync.aligned.m8n8.x4.shared.b16 {%0,%1,%2,%3}, [%4];"
                 : "=r"(r0), "=r"(r1), "=r"(r2), "=r"(r3) : "r"(addr));
}
__device__ __forceinline__ void mma16816(float* c, const uint32_t* a, const uint32_t* b) {
    asm volatile(
        "mma.sync.aligned.m16n8k16.row.col.f32.bf16.bf16.f32 "
        "{%0,%1,%2,%3}, {%4,%5,%6,%7}, {%8,%9}, {%0,%1,%2,%3};"
        : "+f"(c[0]), "+f"(c[1]), "+f"(c[2]), "+f"(c[3])
        : "r"(a[0]), "r"(a[1]), "r"(a[2]), "r"(a[3]), "r"(b[0]), "r"(b[1]));
}

// generic ldmatrix.x4 lane address for a 16x16 bf16 block at (row0, col0)
__device__ __forceinline__ uint32_t ldsm_addr_s(uint32_t base, int row0, int col0,
                                                int lane, int stride) {
    int sub = lane >> 3, r8 = lane & 7;
    int row = row0 + r8 + (sub & 1) * 8;
    int col = col0 + (sub >> 1) * 8;
    return base + (uint32_t)(row * stride + col) * 2;
}

// ============== tensor GEMM (unchanged from R10) ============================
#define TSTR 40
__device__ __forceinline__ void tgemm_tile(const __nv_bfloat16* __restrict__ Ahi,
                                           const __nv_bfloat16* __restrict__ Alo,
                                           const __nv_bfloat16* __restrict__ Bhi,
                                           const __nv_bfloat16* __restrict__ Blo,
                                           float* __restrict__ C, int m0, int n0) {
    __shared__ __nv_bfloat16 sAh[128 * TSTR];
    __shared__ __nv_bfloat16 sAl[128 * TSTR];
    __shared__ __nv_bfloat16 sBh[128 * TSTR];
    __shared__ __nv_bfloat16 sBl[128 * TSTR];

    const int tid  = threadIdx.x;
    const int lane = tid & 31;
    const int wid  = tid >> 5;
    const int wm   = (wid & 1) * 64;
    const int wn   = (wid >> 1) * 32;

    const uint32_t bAh = smem_u32(sAh), bAl = smem_u32(sAl);
    const uint32_t bBh = smem_u32(sBh), bBl = smem_u32(sBl);

    float acc[4][4][4];
#pragma unroll
    for (int i = 0; i < 4; i++)
#pragma unroll
        for (int j = 0; j < 4; j++)
#pragma unroll
            for (int r = 0; r < 4; r++) acc[i][j][r] = 0.f;

    for (int kb = 0; kb < D_MODEL; kb += 32) {
        __syncthreads();
#pragma unroll
        for (int i = 0; i < 2; i++) {
            int li  = tid + i * 256;
            int row = li >> 2;
            int c8  = (li & 3) * 8;
            size_t ga = (size_t)(m0 + row) * D_MODEL + kb + c8;
            size_t gb = (size_t)(n0 + row) * D_MODEL + kb + c8;
            *(uint4*)&sAh[row * TSTR + c8] = *(const uint4*)(Ahi + ga);
            *(uint4*)&sAl[row * TSTR + c8] = *(const uint4*)(Alo + ga);
            *(uint4*)&sBh[row * TSTR + c8] = *(const uint4*)(Bhi + gb);
            *(uint4*)&sBl[row * TSTR + c8] = *(const uint4*)(Blo + gb);
        }
        __syncthreads();

#pragma unroll
        for (int ks = 0; ks < 2; ks++) {
            const int kk = ks * 16;
            uint32_t afh[4][4], afl[4][4];
#pragma unroll
            for (int ma = 0; ma < 4; ma++) {
                ldsm_x4(afh[ma][0], afh[ma][1], afh[ma][2], afh[ma][3],
                        ldsm_addr_s(bAh, wm + ma * 16, kk, lane, TSTR));
                ldsm_x4(afl[ma][0], afl[ma][1], afl[ma][2], afl[ma][3],
                        ldsm_addr_s(bAl, wm + ma * 16, kk, lane, TSTR));
            }
            uint32_t bfh[4][2], bfl[4][2];
#pragma unroll
            for (int p = 0; p < 2; p++) {
                uint32_t r0, r1, r2, r3;
                ldsm_x4(r0, r1, r2, r3, ldsm_addr_s(bBh, wn + p * 16, kk, lane, TSTR));
                bfh[p * 2 + 0][0] = r0; bfh[p * 2 + 0][1] = r2;
                bfh[p * 2 + 1][0] = r1; bfh[p * 2 + 1][1] = r3;
                ldsm_x4(r0, r1, r2, r3, ldsm_addr_s(bBl, wn + p * 16, kk, lane, TSTR));
                bfl[p * 2 + 0][0] = r0; bfl[p * 2 + 0][1] = r2;
                bfl[p * 2 + 1][0] = r1; bfl[p * 2 + 1][1] = r3;
            }
#pragma unroll
            for (int ma = 0; ma < 4; ma++)
#pragma unroll
                for (int na = 0; na < 4; na++) {
                    mma16816(acc[ma][na], afh[ma], bfh[na]);
                    mma16816(acc[ma][na], afh[ma], bfl[na]);
                    mma16816(acc[ma][na], afl[ma], bfh[na]);
                }
        }
    }

#pragma unroll
    for (int ma = 0; ma < 4; ma++)
#pragma unroll
        for (int na = 0; na < 4; na++) {
            int r = m0 + wm + ma * 16 + (lane >> 2);
            int c = n0 + wn + na * 8 + (lane & 3) * 2;
            float* p0 = C + (size_t)r * D_MODEL + c;
            float* p1 = C + (size_t)(r + 8) * D_MODEL + c;
            *(float2*)p0 = make_float2(acc[ma][na][0], acc[ma][na][1]);
            *(float2*)p1 = make_float2(acc[ma][na][2], acc[ma][na][3]);
        }
}

__global__ __launch_bounds__(256) void tgemm_qkv_kernel() {
    int z = blockIdx.z;
    float* C = (z == 0) ? g_q : (z == 1) ? g_k : g_v;
    tgemm_tile(g_xhi, g_xlo, g_whi + (size_t)z * WSZ, g_wlo + (size_t)z * WSZ,
               C, blockIdx.y * 128, blockIdx.x * 128);
}
__global__ __launch_bounds__(256) void tgemm_o_kernel(float* __restrict__ C) {
    tgemm_tile(g_ahi, g_alo, g_whi + (size_t)3 * WSZ, g_wlo + (size_t)3 * WSZ,
               C, blockIdx.y * 128, blockIdx.x * 128);
}

// ================= bf16-split conversions =================
__global__ __launch_bounds__(256) void convert_x_kernel(const float* __restrict__ x) {
    int i = blockIdx.x * 256 + threadIdx.x;
    float v = x[i];
    __nv_bfloat16 hi = __float2bfloat16(v);
    g_xhi[i] = hi;
    g_xlo[i] = __float2bfloat16(v - __bfloat162float(hi));
}
__global__ __launch_bounds__(256) void convert_w_kernel(const float* __restrict__ Wq,
                                                        const float* __restrict__ Wk,
                                                        const float* __restrict__ Wv,
                                                        const float* __restrict__ Wo) {
    int i = blockIdx.x * 256 + threadIdx.x;
    int w = i >> 20;
    int e = i & (WSZ - 1);
    const float* W = (w == 0) ? Wq : (w == 1) ? Wk : (w == 2) ? Wv : Wo;
    float v = W[e];
    __nv_bfloat16 hi = __float2bfloat16(v);
    g_whi[i] = hi;
    g_wlo[i] = __float2bfloat16(v - __bfloat162float(hi));
}

// ========== RoPE table: accurate trig (double path; immune to fast-math) ====
__global__ __launch_bounds__(256) void rope_table_kernel() {
    int idx = blockIdx.x * 256 + threadIdx.x;
    if (idx >= S_LEN * 32) return;
    int d = idx & 31;
    int s = idx >> 5;
    double f64   = pow(10000.0, -(double)d / 32.0);
    float  inv32 = (float)f64;
    float  ang32 = (float)s * inv32;
    double c, sn;
    sincos((double)ang32, &sn, &c);
    g_rope[idx] = make_float2((float)c, (float)sn);
}

// ===== RoPE + bf16-split + head-major relayout for q,k ======================
__global__ __launch_bounds__(256) void ropeconv_kernel() {
    int idx = blockIdx.x * 256 + threadIdx.x;   // M_ROWS*NHEAD*32
    int d    = idx & 31;
    int h    = (idx >> 5) & 15;
    int grow = idx >> 9;               // 0..4095
    int s    = grow & (S_LEN - 1);
    int b    = grow >> 11;

    float2 cs = g_rope[s * 32 + d];
    float c = cs.x, sn = cs.y;

    size_t src = (size_t)grow * D_MODEL + h * HDIM + d;
    float q1 = g_q[src], q2 = g_q[src + 32];
    float k1 = g_k[src], k2 = g_k[src + 32];
    float qa = q1 * c - q2 * sn;
    float qb = q2 * c + q1 * sn;
    float ka = k1 * c - k2 * sn;
    float kb = k2 * c + k1 * sn;

    size_t dst = ((size_t)(b * NHEAD + h) * S_LEN + s) * HDIM + d;
    __nv_bfloat16 t;
    t = __float2bfloat16(qa); g_qhi[dst]      = t; g_qlo[dst]      = __float2bfloat16(qa - __bfloat162float(t));
    t = __float2bfloat16(qb); g_qhi[dst + 32] = t; g_qlo[dst + 32] = __float2bfloat16(qb - __bfloat162float(t));
    t = __float2bfloat16(ka); g_khi[dst]      = t; g_klo[dst]      = __float2bfloat16(ka - __bfloat162float(t));
    t = __float2bfloat16(kb); g_khi[dst + 32] = t; g_klo[dst + 32] = __float2bfloat16(kb - __bfloat162float(t));
}

// ===== V transpose + bf16 split: [s][d] fp32 -> [d][s] hi/lo ================
__global__ __launch_bounds__(256) void vtrans_kernel() {
    __shared__ float tile[64][65];
    int bh = blockIdx.y;               // 0..31
    int s0 = blockIdx.x * 64;
    int b = bh >> 4, h = bh & 15;
    int tid = threadIdx.x;

#pragma unroll
    for (int i = 0; i < 16; i++) {
        int idx = tid + i * 256;       // 0..4095
        int s = idx >> 6, d = idx & 63;
        tile[s][d] = g_v[(size_t)(b * S_LEN + s0 + s) * D_MODEL + h * HDIM + d];
    }
    __syncthreads();
#pragma unroll
    for (int i = 0; i < 16; i++) {
        int idx = tid + i * 256;
        int d = idx >> 6, s = idx & 63;
        float v = tile[s][d];
        __nv_bfloat16 hi = __float2bfloat16(v);
        size_t dst = ((size_t)bh * HDIM + d) * S_LEN + s0 + s;
        g_vthi[dst] = hi;
        g_vtlo[dst] = __float2bfloat16(v - __bfloat162float(hi));
    }
}

// ================= Tensor-core flash attention ==============================
// CTA: (b, h, 128 q rows), 8 warps, warp = one m16 row-atom.
#define ATSTR 72
__global__ __launch_bounds__(256) void attn_tc_kernel() {
    __shared__ __nv_bfloat16 smem[4 * 64 * ATSTR];   // 36,864 B
    __nv_bfloat16* sKh = smem;
    __nv_bfloat16* sKl = smem + 64 * ATSTR;
    __nv_bfloat16* sVh = smem + 2 * 64 * ATSTR;
    __nv_bfloat16* sVl = smem + 3 * 64 * ATSTR;

    const int tid = threadIdx.x, lane = tid & 31, wid = tid >> 5;
    const int b = blockIdx.z, h = blockIdx.y, q0 = blockIdx.x * 128;
    const int bh = b * NHEAD + h;

    const __nv_bfloat16* Qh = g_qhi + (size_t)bh * S_LEN * HDIM;
    const __nv_bfloat16* Ql = g_qlo + (size_t)bh * S_LEN * HDIM;
    const __nv_bfloat16* Kh = g_khi + (size_t)bh * S_LEN * HDIM;
    const __nv_bfloat16* Kl = g_klo + (size_t)bh * S_LEN * HDIM;
    const __nv_bfloat16* Vh = g_vthi + (size_t)bh * HDIM * S_LEN;
    const __nv_bfloat16* Vl = g_vtlo + (size_t)bh * HDIM * S_LEN;

    const uint32_t sb   = smem_u32(smem);
    const uint32_t sbKh = sb, sbKl = sb + 64 * ATSTR * 2;
    const uint32_t sbVh = sb + 2 * 64 * ATSTR * 2, sbVl = sb + 3 * 64 * ATSTR * 2;

    // ---- stage Q and extract fragments (hi then lo) ----
    uint32_t qh[4][4], ql[4][4];
#pragma unroll
    for (int pass = 0; pass < 2; pass++) {
        const __nv_bfloat16* Qsrc = pass ? Ql : Qh;
#pragma unroll
        for (int i = 0; i < 2; i++) {
            int idx = tid + i * 256;         // 0..511
            int row = idx >> 2;              // 0..127
            int c16 = (idx & 3) * 16;        // 0,16,32,48
            *(uint4*)&smem[row * ATSTR + c16]     = *(const uint4*)(Qsrc + (size_t)(q0 + row) * HDIM + c16);
            *(uint4*)&smem[row * ATSTR + c16 + 8] = *(const uint4*)(Qsrc + (size_t)(q0 + row) * HDIM + c16 + 8);
        }
        __syncthreads();
#pragma unroll
        for (int ka = 0; ka < 4; ka++) {
            uint32_t a = ldsm_addr_s(sb, wid * 16, ka * 16, lane, ATSTR);
            if (pass == 0) ldsm_x4(qh[ka][0], qh[ka][1], qh[ka][2], qh[ka][3], a);
            else           ldsm_x4(ql[ka][0], ql[ka][1], ql[ka][2], ql[ka][3], a);
        }
        __syncthreads();
    }

    float out[8][4];
#pragma unroll
    for (int na = 0; na < 8; na++)
#pragma unroll
        for (int r = 0; r < 4; r++) out[na][r] = 0.f;
    float m0 = -INFINITY, m1 = -INFINITY, l0 = 0.f, l1 = 0.f;

    for (int t = 0; t < S_LEN / 64; t++) {
        // load K/V tiles (64x64 each, hi+lo)
#pragma unroll
        for (int i = 0; i < 2; i++) {
            int idx = tid + i * 256;
            int row = idx >> 3;              // 0..63
            int c8  = (idx & 7) * 8;         // 0..56
            size_t gk = (size_t)(t * 64 + row) * HDIM + c8;
            *(uint4*)&sKh[row * ATSTR + c8] = *(const uint4*)(Kh + gk);
            *(uint4*)&sKl[row * ATSTR + c8] = *(const uint4*)(Kl + gk);
            size_t gv = (size_t)row * S_LEN + t * 64 + c8;
            *(uint4*)&sVh[row * ATSTR + c8] = *(const uint4*)(Vh + gv);
            *(uint4*)&sVl[row * ATSTR + c8] = *(const uint4*)(Vl + gv);
        }
        __syncthreads();

        // ---- S = Q K^T (3-term split), 8 n-atoms x 4 k-atoms ----
        float sc[8][4];
#pragma unroll
        for (int na = 0; na < 8; na++)
#pragma unroll
            for (int r = 0; r < 4; r++) sc[na][r] = 0.f;

#pragma unroll
        for (int ka = 0; ka < 4; ka++) {
            uint32_t bkh[8][2], bkl[8][2];
#pragma unroll
            for (int p = 0; p < 4; p++) {
                uint32_t r0, r1, r2, r3;
                ldsm_x4(r0, r1, r2, r3, ldsm_addr_s(sbKh, p * 16, ka * 16, lane, ATSTR));
                bkh[p * 2 + 0][0] = r0; bkh[p * 2 + 0][1] = r2;
                bkh[p * 2 + 1][0] = r1; bkh[p * 2 + 1][1] = r3;
                ldsm_x4(r0, r1, r2, r3, ldsm_addr_s(sbKl, p * 16, ka * 16, lane, ATSTR));
                bkl[p * 2 + 0][0] = r0; bkl[p * 2 + 0][1] = r2;
                bkl[p * 2 + 1][0] = r1; bkl[p * 2 + 1][1] = r3;
            }
#pragma unroll
            for (int na = 0; na < 8; na++) {
                mma16816(sc[na], qh[ka], bkh[na]);
                mma16816(sc[na], qh[ka], bkl[na]);
                mma16816(sc[na], ql[ka], bkh[na]);
            }
        }

        // ---- online softmax in accumulator layout ----
        float mt0 = -INFINITY, mt1 = -INFINITY;
#pragma unroll
        for (int na = 0; na < 8; na++) {
#pragma unroll
            for (int r = 0; r < 4; r++) sc[na][r] *= 0.125f;
            mt0 = fmaxf(mt0, fmaxf(sc[na][0], sc[na][1]));
            mt1 = fmaxf(mt1, fmaxf(sc[na][2], sc[na][3]));
        }
        mt0 = fmaxf(mt0, __shfl_xor_sync(0xffffffffu, mt0, 1));
        mt0 = fmaxf(mt0, __shfl_xor_sync(0xffffffffu, mt0, 2));
        mt1 = fmaxf(mt1, __shfl_xor_sync(0xffffffffu, mt1, 1));
        mt1 = fmaxf(mt1, __shfl_xor_sync(0xffffffffu, mt1, 2));

        float mn0 = fmaxf(m0, mt0), mn1 = fmaxf(m1, mt1);
        float al0 = __expf(m0 - mn0), al1 = __expf(m1 - mn1);
        m0 = mn0; m1 = mn1;

        uint32_t pA[8], pB[8], pAl[8], pBl[8];
        float rs0 = 0.f, rs1 = 0.f;
#pragma unroll
        for (int na = 0; na < 8; na++) {
            float p00 = __expf(sc[na][0] - m0);
            float p01 = __expf(sc[na][1] - m0);
            float p10 = __expf(sc[na][2] - m1);
            float p11 = __expf(sc[na][3] - m1);
            rs0 += p00 + p01; rs1 += p10 + p11;
            __nv_bfloat162 hv, lv;
            hv.x = __float2bfloat16(p00); hv.y = __float2bfloat16(p01);
            lv.x = __float2bfloat16(p00 - __bfloat162float(hv.x));
            lv.y = __float2bfloat16(p01 - __bfloat162float(hv.y));
            pA[na] = *(uint32_t*)&hv; pAl[na] = *(uint32_t*)&lv;
            hv.x = __float2bfloat16(p10); hv.y = __float2bfloat16(p11);
            lv.x = __float2bfloat16(p10 - __bfloat162float(hv.x));
            lv.y = __float2bfloat16(p11 - __bfloat162float(hv.y));
            pB[na] = *(uint32_t*)&hv; pBl[na] = *(uint32_t*)&lv;
        }
        rs0 += __shfl_xor_sync(0xffffffffu, rs0, 1);
        rs0 += __shfl_xor_sync(0xffffffffu, rs0, 2);
        rs1 += __shfl_xor_sync(0xffffffffu, rs1, 1);
        rs1 += __shfl_xor_sync(0xffffffffu, rs1, 2);
        l0 = l0 * al0 + rs0;
        l1 = l1 * al1 + rs1;
#pragma unroll
        for (int na = 0; na < 8; na++) {
            out[na][0] *= al0; out[na][1] *= al0;
            out[na][2] *= al1; out[na][3] *= al1;
        }

        // ---- out += P V (3-term split), n-atoms over HDIM ----
#pragma unroll
        for (int ka = 0; ka < 4; ka++) {
            uint32_t ah[4]  = {pA[2 * ka],  pB[2 * ka],  pA[2 * ka + 1],  pB[2 * ka + 1]};
            uint32_t alo[4] = {pAl[2 * ka], pBl[2 * ka], pAl[2 * ka + 1], pBl[2 * ka + 1]};
            uint32_t bvh[8][2], bvl[8][2];
#pragma unroll
            for (int p = 0; p < 4; p++) {
                uint32_t r0, r1, r2, r3;
                ldsm_x4(r0, r1, r2, r3, ldsm_addr_s(sbVh, p * 16, ka * 16, lane, ATSTR));
                bvh[p * 2 + 0][0] = r0; bvh[p * 2 + 0][1] = r2;
                bvh[p * 2 + 1][0] = r1; bvh[p * 2 + 1][1] = r3;
                ldsm_x4(r0, r1, r2, r3, ldsm_addr_s(sbVl, p * 16, ka * 16, lane, ATSTR));
                bvl[p * 2 + 0][0] = r0; bvl[p * 2 + 0][1] = r2;
                bvl[p * 2 + 1][0] = r1; bvl[p * 2 + 1][1] = r3;
            }
#pragma unroll
            for (int na = 0; na < 8; na++) {
                mma16816(out[na], ah,  bvh[na]);
                mma16816(out[na], ah,  bvl[na]);
                mma16816(out[na], alo, bvh[na]);
            }
        }
        __syncthreads();
    }

    // ---- epilogue: normalize, bf16-split, write g_ahi/g_alo ----
    float inv0 = 1.f / l0, inv1 = 1.f / l1;
    int gr  = lane >> 2;
    int gc2 = (lane & 3) * 2;
    int row0 = b * S_LEN + q0 + wid * 16 + gr;
#pragma unroll
    for (int na = 0; na < 8; na++) {
        int col = h * HDIM + na * 8 + gc2;
        float v0 = out[na][0] * inv0, v1 = out[na][1] * inv0;
        float v2 = out[na][2] * inv1, v3 = out[na][3] * inv1;
        __nv_bfloat162 hv, lv;
        hv.x = __float2bfloat16(v0); hv.y = __float2bfloat16(v1);
        lv.x = __float2bfloat16(v0 - __bfloat162float(hv.x));
        lv.y = __float2bfloat16(v1 - __bfloat162float(hv.y));
        *(__nv_bfloat162*)&g_ahi[(size_t)row0 * D_MODEL + col] = hv;
        *(__nv_bfloat162*)&g_alo[(size_t)row0 * D_MODEL + col] = lv;
        hv.x = __float2bfloat16(v2); hv.y = __float2bfloat16(v3);
        lv.x = __float2bfloat16(v2 - __bfloat162float(hv.x));
        lv.y = __float2bfloat16(v3 - __bfloat162float(hv.y));
        *(__nv_bfloat162*)&g_ahi[(size_t)(row0 + 8) * D_MODEL + col] = hv;
        *(__nv_bfloat162*)&g_alo[(size_t)(row0 + 8) * D_MODEL + col] = lv;
    }
}

// ================= launch =================
extern "C" void kernel_launch(void* const* d_in, const int* in_sizes, int n_in,
                              void* d_out, int out_size) {
    int xi = -1;
    for (int i = 0; i < n_in; i++)
        if (in_sizes[i] == M_ROWS * D_MODEL) { xi = i; break; }
    if (xi < 0) xi = 0;
    const float* w[4] = {0, 0, 0, 0};
    int wn = 0;
    for (int i = 0; i < n_in && wn < 4; i++)
        if (i != xi && in_sizes[i] == WSZ)
            w[wn++] = (const float*)d_in[i];

    const float* x  = (const float*)d_in[xi];
    float* out = (float*)d_out;

    convert_x_kernel<<<(M_ROWS * D_MODEL) / 256, 256>>>(x);
    convert_w_kernel<<<(4 * WSZ) / 256, 256>>>(w[0], w[1], w[2], w[3]);

    dim3 gqkv(D_MODEL / 128, M_ROWS / 128, 3);
    tgemm_qkv_kernel<<<gqkv, 256>>>();

    rope_table_kernel<<<(S_LEN * 32) / 256, 256>>>();
    ropeconv_kernel<<<(M_ROWS * NHEAD * 32) / 256, 256>>>();

    dim3 gvt(S_LEN / 64, HS, 1);
    vtrans_kernel<<<gvt, 256>>>();

    dim3 gattn(S_LEN / 128, NHEAD, B_SZ);    // (16, 16, 2)
    attn_tc_kernel<<<gattn, 256>>>();

    dim3 go(D_MODEL / 128, M_ROWS / 128, 1);
    tgemm_o_kernel<<<go, 256>>>(out);
}

// round 12
// speedup vs baseline: 4.8454x; 1.1022x over previous
#include <cuda_runtime.h>
#include <cuda_bf16.h>
#include <math.h>
#include <stdint.h>

#define B_SZ    2
#define S_LEN   2048
#define D_MODEL 1024
#define NHEAD   16
#define HDIM    64
#define M_ROWS  (B_SZ * S_LEN)   // 4096
#define WSZ     (D_MODEL * D_MODEL)   // 1M
#define HS      (B_SZ * NHEAD)   // 32 heads total

// ---------------- scratch (device-side only) ----------------
__device__ float  g_q[M_ROWS * D_MODEL];
__device__ float  g_k[M_ROWS * D_MODEL];
__device__ float  g_v[M_ROWS * D_MODEL];
__device__ float2 g_rope[S_LEN * 32];
__device__ __nv_bfloat16 g_xhi[M_ROWS * D_MODEL];
__device__ __nv_bfloat16 g_xlo[M_ROWS * D_MODEL];
__device__ __nv_bfloat16 g_whi[4 * WSZ];
__device__ __nv_bfloat16 g_wlo[4 * WSZ];
__device__ __nv_bfloat16 g_ahi[M_ROWS * D_MODEL];
__device__ __nv_bfloat16 g_alo[M_ROWS * D_MODEL];
__device__ __nv_bfloat16 g_qhi[HS * S_LEN * HDIM];
__device__ __nv_bfloat16 g_qlo[HS * S_LEN * HDIM];
__device__ __nv_bfloat16 g_khi[HS * S_LEN * HDIM];
__device__ __nv_bfloat16 g_klo[HS * S_LEN * HDIM];
__device__ __nv_bfloat16 g_vthi[HS * HDIM * S_LEN];
__device__ __nv_bfloat16 g_vtlo[HS * HDIM * S_LEN];

// ================= helpers =================
__device__ __forceinline__ uint32_t smem_u32(const void* p) {
    uint32_t a;
    asm("{ .reg .u64 t; cvta.to.shared.u64 t, %1; cvt.u32.u64 %0, t; }" : "=r"(a) : "l"(p));
    return a;
}
__device__ __forceinline__ void ldsm_x4(uint32_t& r0, uint32_t& r1, uint32_t& r2, uint32_t& r3,
                                        uint32_t addr) {
    asm volatile("ldmatrix.sync.aligned.m8n8.x4.shared.b16 {%0,%1,%2,%3}, [%4];"
                 : "=r"(r0), "=r"(r1), "=r"(r2), "=r"(r3) : "r"(addr));
}
__device__ __forceinline__ void mma16816(float* c, const uint32_t* a, const uint32_t* b) {
    asm volatile(
        "mma.sync.aligned.m16n8k16.row.col.f32.bf16.bf16.f32 "
        "{%0,%1,%2,%3}, {%4,%5,%6,%7}, {%8,%9}, {%0,%1,%2,%3};"
        : "+f"(c[0]), "+f"(c[1]), "+f"(c[2]), "+f"(c[3])
        : "r"(a[0]), "r"(a[1]), "r"(a[2]), "r"(a[3]), "r"(b[0]), "r"(b[1]));
}
__device__ __forceinline__ void cp16(uint32_t dst, const void* src) {
    asm volatile("cp.async.cg.shared.global [%0], [%1], 16;" :: "r"(dst), "l"(src));
}
#define CP_COMMIT() asm volatile("cp.async.commit_group;" ::: "memory")
#define CP_WAIT1()  asm volatile("cp.async.wait_group 1;" ::: "memory")

__device__ __forceinline__ uint32_t ldsm_addr_s(uint32_t base, int row0, int col0,
                                                int lane, int stride) {
    int sub = lane >> 3, r8 = lane & 7;
    int row = row0 + r8 + (sub & 1) * 8;
    int col = col0 + (sub >> 1) * 8;
    return base + (uint32_t)(row * stride + col) * 2;
}

// ============== pipelined tensor GEMM ======================================
#define TSTR 40
#define STG  (128 * TSTR)                 // elems per buffer
#define GEMM_SMEM (2 * 4 * STG * 2)       // 81920 B

__device__ __forceinline__ void gemm_stage_load(__nv_bfloat16* st,
                                                const __nv_bfloat16* Ahi,
                                                const __nv_bfloat16* Alo,
                                                const __nv_bfloat16* Bhi,
                                                const __nv_bfloat16* Blo,
                                                int m0, int n0, int kb, int tid) {
    uint32_t b0 = smem_u32(st);
#pragma unroll
    for (int i = 0; i < 2; i++) {
        int li  = tid + i * 256;
        int row = li >> 2;
        int c8  = (li & 3) * 8;
        uint32_t so = (uint32_t)(row * TSTR + c8) * 2;
        size_t ga = (size_t)(m0 + row) * D_MODEL + kb + c8;
        size_t gb = (size_t)(n0 + row) * D_MODEL + kb + c8;
        cp16(b0 + so,               Ahi + ga);
        cp16(b0 + STG * 2 + so,     Alo + ga);
        cp16(b0 + STG * 4 + so,     Bhi + gb);
        cp16(b0 + STG * 6 + so,     Blo + gb);
    }
}

__device__ __forceinline__ void tgemm_tile(const __nv_bfloat16* __restrict__ Ahi,
                                           const __nv_bfloat16* __restrict__ Alo,
                                           const __nv_bfloat16* __restrict__ Bhi,
                                           const __nv_bfloat16* __restrict__ Blo,
                                           float* __restrict__ C, int m0, int n0) {
    extern __shared__ __nv_bfloat16 dsm[];
    const int tid  = threadIdx.x;
    const int lane = tid & 31;
    const int wid  = tid >> 5;
    const int wm   = (wid & 1) * 64;
    const int wn   = (wid >> 1) * 32;

    float acc[4][4][4];
#pragma unroll
    for (int i = 0; i < 4; i++)
#pragma unroll
        for (int j = 0; j < 4; j++)
#pragma unroll
            for (int r = 0; r < 4; r++) acc[i][j][r] = 0.f;

    gemm_stage_load(dsm, Ahi, Alo, Bhi, Blo, m0, n0, 0, tid);
    CP_COMMIT();

    for (int ch = 0; ch < 32; ch++) {
        if (ch < 31)
            gemm_stage_load(dsm + ((ch + 1) & 1) * 4 * STG, Ahi, Alo, Bhi, Blo,
                            m0, n0, (ch + 1) * 32, tid);
        CP_COMMIT();
        CP_WAIT1();
        __syncthreads();

        uint32_t b0  = smem_u32(dsm + (ch & 1) * 4 * STG);
        uint32_t bAh = b0, bAl = b0 + STG * 2, bBh = b0 + STG * 4, bBl = b0 + STG * 6;

#pragma unroll
        for (int ks = 0; ks < 2; ks++) {
            const int kk = ks * 16;
            uint32_t afh[4][4], afl[4][4];
#pragma unroll
            for (int ma = 0; ma < 4; ma++) {
                ldsm_x4(afh[ma][0], afh[ma][1], afh[ma][2], afh[ma][3],
                        ldsm_addr_s(bAh, wm + ma * 16, kk, lane, TSTR));
                ldsm_x4(afl[ma][0], afl[ma][1], afl[ma][2], afl[ma][3],
                        ldsm_addr_s(bAl, wm + ma * 16, kk, lane, TSTR));
            }
            uint32_t bfh[4][2], bfl[4][2];
#pragma unroll
            for (int p = 0; p < 2; p++) {
                uint32_t r0, r1, r2, r3;
                ldsm_x4(r0, r1, r2, r3, ldsm_addr_s(bBh, wn + p * 16, kk, lane, TSTR));
                bfh[p * 2 + 0][0] = r0; bfh[p * 2 + 0][1] = r2;
                bfh[p * 2 + 1][0] = r1; bfh[p * 2 + 1][1] = r3;
                ldsm_x4(r0, r1, r2, r3, ldsm_addr_s(bBl, wn + p * 16, kk, lane, TSTR));
                bfl[p * 2 + 0][0] = r0; bfl[p * 2 + 0][1] = r2;
                bfl[p * 2 + 1][0] = r1; bfl[p * 2 + 1][1] = r3;
            }
#pragma unroll
            for (int ma = 0; ma < 4; ma++)
#pragma unroll
                for (int na = 0; na < 4; na++) {
                    mma16816(acc[ma][na], afh[ma], bfh[na]);
                    mma16816(acc[ma][na], afh[ma], bfl[na]);
                    mma16816(acc[ma][na], afl[ma], bfh[na]);
                }
        }
        __syncthreads();
    }

#pragma unroll
    for (int ma = 0; ma < 4; ma++)
#pragma unroll
        for (int na = 0; na < 4; na++) {
            int r = m0 + wm + ma * 16 + (lane >> 2);
            int c = n0 + wn + na * 8 + (lane & 3) * 2;
            *(float2*)(C + (size_t)r * D_MODEL + c)       = make_float2(acc[ma][na][0], acc[ma][na][1]);
            *(float2*)(C + (size_t)(r + 8) * D_MODEL + c) = make_float2(acc[ma][na][2], acc[ma][na][3]);
        }
}

__global__ __launch_bounds__(256) void tgemm_qkv_kernel() {
    int z = blockIdx.z;
    float* C = (z == 0) ? g_q : (z == 1) ? g_k : g_v;
    tgemm_tile(g_xhi, g_xlo, g_whi + (size_t)z * WSZ, g_wlo + (size_t)z * WSZ,
               C, blockIdx.y * 128, blockIdx.x * 128);
}
__global__ __launch_bounds__(256) void tgemm_o_kernel(float* __restrict__ C) {
    tgemm_tile(g_ahi, g_alo, g_whi + (size_t)3 * WSZ, g_wlo + (size_t)3 * WSZ,
               C, blockIdx.y * 128, blockIdx.x * 128);
}

// ================= bf16-split conversions =================
__global__ __launch_bounds__(256) void convert_x_kernel(const float* __restrict__ x) {
    int i = blockIdx.x * 256 + threadIdx.x;
    float v = x[i];
    __nv_bfloat16 hi = __float2bfloat16(v);
    g_xhi[i] = hi;
    g_xlo[i] = __float2bfloat16(v - __bfloat162float(hi));
}
__global__ __launch_bounds__(256) void convert_w_kernel(const float* __restrict__ Wq,
                                                        const float* __restrict__ Wk,
                                                        const float* __restrict__ Wv,
                                                        const float* __restrict__ Wo) {
    int i = blockIdx.x * 256 + threadIdx.x;
    int w = i >> 20;
    int e = i & (WSZ - 1);
    const float* W = (w == 0) ? Wq : (w == 1) ? Wk : (w == 2) ? Wv : Wo;
    float v = W[e];
    __nv_bfloat16 hi = __float2bfloat16(v);
    g_whi[i] = hi;
    g_wlo[i] = __float2bfloat16(v - __bfloat162float(hi));
}

// ========== RoPE table (accurate double trig; immune to fast-math) ==========
__global__ __launch_bounds__(256) void rope_table_kernel() {
    int idx = blockIdx.x * 256 + threadIdx.x;
    if (idx >= S_LEN * 32) return;
    int d = idx & 31;
    int s = idx >> 5;
    double f64   = pow(10000.0, -(double)d / 32.0);
    float  inv32 = (float)f64;
    float  ang32 = (float)s * inv32;
    double c, sn;
    sincos((double)ang32, &sn, &c);
    g_rope[idx] = make_float2((float)c, (float)sn);
}

// ===== RoPE + bf16-split + head-major relayout for q,k ======================
__global__ __launch_bounds__(256) void ropeconv_kernel() {
    int idx = blockIdx.x * 256 + threadIdx.x;
    int d    = idx & 31;
    int h    = (idx >> 5) & 15;
    int grow = idx >> 9;
    int s    = grow & (S_LEN - 1);
    int b    = grow >> 11;

    float2 cs = g_rope[s * 32 + d];
    float c = cs.x, sn = cs.y;

    size_t src = (size_t)grow * D_MODEL + h * HDIM + d;
    float q1 = g_q[src], q2 = g_q[src + 32];
    float k1 = g_k[src], k2 = g_k[src + 32];
    float qa = q1 * c - q2 * sn;
    float qb = q2 * c + q1 * sn;
    float ka = k1 * c - k2 * sn;
    float kb = k2 * c + k1 * sn;

    size_t dst = ((size_t)(b * NHEAD + h) * S_LEN + s) * HDIM + d;
    __nv_bfloat16 t;
    t = __float2bfloat16(qa); g_qhi[dst]      = t; g_qlo[dst]      = __float2bfloat16(qa - __bfloat162float(t));
    t = __float2bfloat16(qb); g_qhi[dst + 32] = t; g_qlo[dst + 32] = __float2bfloat16(qb - __bfloat162float(t));
    t = __float2bfloat16(ka); g_khi[dst]      = t; g_klo[dst]      = __float2bfloat16(ka - __bfloat162float(t));
    t = __float2bfloat16(kb); g_khi[dst + 32] = t; g_klo[dst + 32] = __float2bfloat16(kb - __bfloat162float(t));
}

// ===== V transpose + bf16 split =============================================
__global__ __launch_bounds__(256) void vtrans_kernel() {
    __shared__ float tile[64][65];
    int bh = blockIdx.y;
    int s0 = blockIdx.x * 64;
    int b = bh >> 4, h = bh & 15;
    int tid = threadIdx.x;

#pragma unroll
    for (int i = 0; i < 16; i++) {
        int idx = tid + i * 256;
        int s = idx >> 6, d = idx & 63;
        tile[s][d] = g_v[(size_t)(b * S_LEN + s0 + s) * D_MODEL + h * HDIM + d];
    }
    __syncthreads();
#pragma unroll
    for (int i = 0; i < 16; i++) {
        int idx = tid + i * 256;
        int d = idx >> 6, s = idx & 63;
        float v = tile[s][d];
        __nv_bfloat16 hi = __float2bfloat16(v);
        size_t dst = ((size_t)bh * HDIM + d) * S_LEN + s0 + s;
        g_vthi[dst] = hi;
        g_vtlo[dst] = __float2bfloat16(v - __bfloat162float(hi));
    }
}

// ================= Tensor-core flash attention (pipelined) ==================
#define ATSTR 72
#define ASTG  (64 * ATSTR)
#define ATTN_SMEM (2 * 4 * ASTG * 2)     // 73728 B

__global__ __launch_bounds__(256) void attn_tc_kernel() {
    extern __shared__ __nv_bfloat16 adsm[];
    const int tid = threadIdx.x, lane = tid & 31, wid = tid >> 5;
    const int b = blockIdx.z, h = blockIdx.y, q0 = blockIdx.x * 128;
    const int bh = b * NHEAD + h;

    const __nv_bfloat16* Qh = g_qhi + (size_t)bh * S_LEN * HDIM;
    const __nv_bfloat16* Ql = g_qlo + (size_t)bh * S_LEN * HDIM;
    const __nv_bfloat16* Kh = g_khi + (size_t)bh * S_LEN * HDIM;
    const __nv_bfloat16* Kl = g_klo + (size_t)bh * S_LEN * HDIM;
    const __nv_bfloat16* Vh = g_vthi + (size_t)bh * HDIM * S_LEN;
    const __nv_bfloat16* Vl = g_vtlo + (size_t)bh * HDIM * S_LEN;

    // ---- stage Q in stage-0 smem region and extract fragments ----
    uint32_t qh[4][4], ql[4][4];
    {
        const uint32_t sb = smem_u32(adsm);
#pragma unroll
        for (int pass = 0; pass < 2; pass++) {
            const __nv_bfloat16* Qsrc = pass ? Ql : Qh;
#pragma unroll
            for (int i = 0; i < 2; i++) {
                int idx = tid + i * 256;
                int row = idx >> 2;
                int c16 = (idx & 3) * 16;
                *(uint4*)&adsm[row * ATSTR + c16]     = *(const uint4*)(Qsrc + (size_t)(q0 + row) * HDIM + c16);
                *(uint4*)&adsm[row * ATSTR + c16 + 8] = *(const uint4*)(Qsrc + (size_t)(q0 + row) * HDIM + c16 + 8);
            }
            __syncthreads();
#pragma unroll
            for (int ka = 0; ka < 4; ka++) {
                uint32_t a = ldsm_addr_s(sb, wid * 16, ka * 16, lane, ATSTR);
                if (pass == 0) ldsm_x4(qh[ka][0], qh[ka][1], qh[ka][2], qh[ka][3], a);
                else           ldsm_x4(ql[ka][0], ql[ka][1], ql[ka][2], ql[ka][3], a);
            }
            __syncthreads();
        }
    }

    float out[8][4];
#pragma unroll
    for (int na = 0; na < 8; na++)
#pragma unroll
        for (int r = 0; r < 4; r++) out[na][r] = 0.f;
    float m0 = -INFINITY, m1 = -INFINITY, l0 = 0.f, l1 = 0.f;

    // ---- stage loader ----
    auto stage_load = [&](int st, int t) {
        uint32_t b0 = smem_u32(adsm + st * 4 * ASTG);
#pragma unroll
        for (int i = 0; i < 2; i++) {
            int idx = tid + i * 256;
            int row = idx >> 3;
            int c8  = (idx & 7) * 8;
            uint32_t so = (uint32_t)(row * ATSTR + c8) * 2;
            size_t gk = (size_t)(t * 64 + row) * HDIM + c8;
            size_t gv = (size_t)row * S_LEN + t * 64 + c8;
            cp16(b0 + so,                Kh + gk);
            cp16(b0 + ASTG * 2 + so,     Kl + gk);
            cp16(b0 + ASTG * 4 + so,     Vh + gv);
            cp16(b0 + ASTG * 6 + so,     Vl + gv);
        }
    };

    stage_load(0, 0);
    CP_COMMIT();

    for (int t = 0; t < S_LEN / 64; t++) {
        if (t < S_LEN / 64 - 1) stage_load((t + 1) & 1, t + 1);
        CP_COMMIT();
        CP_WAIT1();
        __syncthreads();

        uint32_t b0   = smem_u32(adsm + (t & 1) * 4 * ASTG);
        uint32_t sbKh = b0, sbKl = b0 + ASTG * 2, sbVh = b0 + ASTG * 4, sbVl = b0 + ASTG * 6;

        // ---- S = Q K^T (3-term split) ----
        float sc[8][4];
#pragma unroll
        for (int na = 0; na < 8; na++)
#pragma unroll
            for (int r = 0; r < 4; r++) sc[na][r] = 0.f;

#pragma unroll
        for (int ka = 0; ka < 4; ka++) {
            uint32_t bkh[8][2], bkl[8][2];
#pragma unroll
            for (int p = 0; p < 4; p++) {
                uint32_t r0, r1, r2, r3;
                ldsm_x4(r0, r1, r2, r3, ldsm_addr_s(sbKh, p * 16, ka * 16, lane, ATSTR));
                bkh[p * 2 + 0][0] = r0; bkh[p * 2 + 0][1] = r2;
                bkh[p * 2 + 1][0] = r1; bkh[p * 2 + 1][1] = r3;
                ldsm_x4(r0, r1, r2, r3, ldsm_addr_s(sbKl, p * 16, ka * 16, lane, ATSTR));
                bkl[p * 2 + 0][0] = r0; bkl[p * 2 + 0][1] = r2;
                bkl[p * 2 + 1][0] = r1; bkl[p * 2 + 1][1] = r3;
            }
#pragma unroll
            for (int na = 0; na < 8; na++) {
                mma16816(sc[na], qh[ka], bkh[na]);
                mma16816(sc[na], qh[ka], bkl[na]);
                mma16816(sc[na], ql[ka], bkh[na]);
            }
        }

        // ---- online softmax ----
        float mt0 = -INFINITY, mt1 = -INFINITY;
#pragma unroll
        for (int na = 0; na < 8; na++) {
#pragma unroll
            for (int r = 0; r < 4; r++) sc[na][r] *= 0.125f;
            mt0 = fmaxf(mt0, fmaxf(sc[na][0], sc[na][1]));
            mt1 = fmaxf(mt1, fmaxf(sc[na][2], sc[na][3]));
        }
        mt0 = fmaxf(mt0, __shfl_xor_sync(0xffffffffu, mt0, 1));
        mt0 = fmaxf(mt0, __shfl_xor_sync(0xffffffffu, mt0, 2));
        mt1 = fmaxf(mt1, __shfl_xor_sync(0xffffffffu, mt1, 1));
        mt1 = fmaxf(mt1, __shfl_xor_sync(0xffffffffu, mt1, 2));

        float mn0 = fmaxf(m0, mt0), mn1 = fmaxf(m1, mt1);
        float al0 = __expf(m0 - mn0), al1 = __expf(m1 - mn1);
        m0 = mn0; m1 = mn1;

        uint32_t pA[8], pB[8], pAl[8], pBl[8];
        float rs0 = 0.f, rs1 = 0.f;
#pragma unroll
        for (int na = 0; na < 8; na++) {
            float p00 = __expf(sc[na][0] - m0);
            float p01 = __expf(sc[na][1] - m0);
            float p10 = __expf(sc[na][2] - m1);
            float p11 = __expf(sc[na][3] - m1);
            rs0 += p00 + p01; rs1 += p10 + p11;
            __nv_bfloat162 hv, lv;
            hv.x = __float2bfloat16(p00); hv.y = __float2bfloat16(p01);
            lv.x = __float2bfloat16(p00 - __bfloat162float(hv.x));
            lv.y = __float2bfloat16(p01 - __bfloat162float(hv.y));
            pA[na] = *(uint32_t*)&hv; pAl[na] = *(uint32_t*)&lv;
            hv.x = __float2bfloat16(p10); hv.y = __float2bfloat16(p11);
            lv.x = __float2bfloat16(p10 - __bfloat162float(hv.x));
            lv.y = __float2bfloat16(p11 - __bfloat162float(hv.y));
            pB[na] = *(uint32_t*)&hv; pBl[na] = *(uint32_t*)&lv;
        }
        rs0 += __shfl_xor_sync(0xffffffffu, rs0, 1);
        rs0 += __shfl_xor_sync(0xffffffffu, rs0, 2);
        rs1 += __shfl_xor_sync(0xffffffffu, rs1, 1);
        rs1 += __shfl_xor_sync(0xffffffffu, rs1, 2);
        l0 = l0 * al0 + rs0;
        l1 = l1 * al1 + rs1;
#pragma unroll
        for (int na = 0; na < 8; na++) {
            out[na][0] *= al0; out[na][1] *= al0;
            out[na][2] *= al1; out[na][3] *= al1;
        }

        // ---- out += P V (3-term split) ----
#pragma unroll
        for (int ka = 0; ka < 4; ka++) {
            uint32_t ah[4]  = {pA[2 * ka],  pB[2 * ka],  pA[2 * ka + 1],  pB[2 * ka + 1]};
            uint32_t alo[4] = {pAl[2 * ka], pBl[2 * ka], pAl[2 * ka + 1], pBl[2 * ka + 1]};
            uint32_t bvh[8][2], bvl[8][2];
#pragma unroll
            for (int p = 0; p < 4; p++) {
                uint32_t r0, r1, r2, r3;
                ldsm_x4(r0, r1, r2, r3, ldsm_addr_s(sbVh, p * 16, ka * 16, lane, ATSTR));
                bvh[p * 2 + 0][0] = r0; bvh[p * 2 + 0][1] = r2;
                bvh[p * 2 + 1][0] = r1; bvh[p * 2 + 1][1] = r3;
                ldsm_x4(r0, r1, r2, r3, ldsm_addr_s(sbVl, p * 16, ka * 16, lane, ATSTR));
                bvl[p * 2 + 0][0] = r0; bvl[p * 2 + 0][1] = r2;
                bvl[p * 2 + 1][0] = r1; bvl[p * 2 + 1][1] = r3;
            }
#pragma unroll
            for (int na = 0; na < 8; na++) {
                mma16816(out[na], ah,  bvh[na]);
                mma16816(out[na], ah,  bvl[na]);
                mma16816(out[na], alo, bvh[na]);
            }
        }
        __syncthreads();
    }

    // ---- epilogue ----
    float inv0 = 1.f / l0, inv1 = 1.f / l1;
    int gr  = lane >> 2;
    int gc2 = (lane & 3) * 2;
    int row0 = b * S_LEN + q0 + wid * 16 + gr;
#pragma unroll
    for (int na = 0; na < 8; na++) {
        int col = h * HDIM + na * 8 + gc2;
        float v0 = out[na][0] * inv0, v1 = out[na][1] * inv0;
        float v2 = out[na][2] * inv1, v3 = out[na][3] * inv1;
        __nv_bfloat162 hv, lv;
        hv.x = __float2bfloat16(v0); hv.y = __float2bfloat16(v1);
        lv.x = __float2bfloat16(v0 - __bfloat162float(hv.x));
        lv.y = __float2bfloat16(v1 - __bfloat162float(hv.y));
        *(__nv_bfloat162*)&g_ahi[(size_t)row0 * D_MODEL + col] = hv;
        *(__nv_bfloat162*)&g_alo[(size_t)row0 * D_MODEL + col] = lv;
        hv.x = __float2bfloat16(v2); hv.y = __float2bfloat16(v3);
        lv.x = __float2bfloat16(v2 - __bfloat162float(hv.x));
        lv.y = __float2bfloat16(v3 - __bfloat162float(hv.y));
        *(__nv_bfloat162*)&g_ahi[(size_t)(row0 + 8) * D_MODEL + col] = hv;
        *(__nv_bfloat162*)&g_alo[(size_t)(row0 + 8) * D_MODEL + col] = lv;
    }
}

// ================= launch =================
extern "C" void kernel_launch(void* const* d_in, const int* in_sizes, int n_in,
                              void* d_out, int out_size) {
    int xi = -1;
    for (int i = 0; i < n_in; i++)
        if (in_sizes[i] == M_ROWS * D_MODEL) { xi = i; break; }
    if (xi < 0) xi = 0;
    const float* w[4] = {0, 0, 0, 0};
    int wn = 0;
    for (int i = 0; i < n_in && wn < 4; i++)
        if (i != xi && in_sizes[i] == WSZ)
            w[wn++] = (const float*)d_in[i];

    const float* x  = (const float*)d_in[xi];
    float* out = (float*)d_out;

    cudaFuncSetAttribute(tgemm_qkv_kernel, cudaFuncAttributeMaxDynamicSharedMemorySize, GEMM_SMEM);
    cudaFuncSetAttribute(tgemm_o_kernel,   cudaFuncAttributeMaxDynamicSharedMemorySize, GEMM_SMEM);
    cudaFuncSetAttribute(attn_tc_kernel,   cudaFuncAttributeMaxDynamicSharedMemorySize, ATTN_SMEM);

    convert_x_kernel<<<(M_ROWS * D_MODEL) / 256, 256>>>(x);
    convert_w_kernel<<<(4 * WSZ) / 256, 256>>>(w[0], w[1], w[2], w[3]);

    dim3 gqkv(D_MODEL / 128, M_ROWS / 128, 3);
    tgemm_qkv_kernel<<<gqkv, 256, GEMM_SMEM>>>();

    rope_table_kernel<<<(S_LEN * 32) / 256, 256>>>();
    ropeconv_kernel<<<(M_ROWS * NHEAD * 32) / 256, 256>>>();

    dim3 gvt(S_LEN / 64, HS, 1);
    vtrans_kernel<<<gvt, 256>>>();

    dim3 gattn(S_LEN / 128, NHEAD, B_SZ);
    attn_tc_kernel<<<gattn, 256, ATTN_SMEM>>>();

    dim3 go(D_MODEL / 128, M_ROWS / 128, 1);
    tgemm_o_kernel<<<go, 256, GEMM_SMEM>>>(out);
}